// round 1
// baseline (speedup 1.0000x reference)
#include <cuda_runtime.h>
#include <cuda_bf16.h>

// Problem constants
#define B_ROWS   16384
#define IN_DIM   1024
#define OUT_DIM  1024
#define NGRID    9          // NUM_SEGMENTS + 1
#define GRID_LO  (-1.0f)
#define HSTEP    0.25f      // (HI - LO) / NUM_SEGMENTS

// Normalized hat weights per row: w[B_ROWS][NGRID]
__device__ float g_w[B_ROWS * NGRID];

// ---------------------------------------------------------------------------
// f32x2 packed helpers (B300: 2x fp32 FMA rate, only reachable via PTX)
// ---------------------------------------------------------------------------
__device__ __forceinline__ unsigned long long pack2(float x, float y) {
    unsigned long long r;
    asm("mov.b64 %0, {%1, %2};" : "=l"(r) : "f"(x), "f"(y));
    return r;
}
__device__ __forceinline__ void unpack2(unsigned long long v, float &x, float &y) {
    asm("mov.b64 {%0, %1}, %2;" : "=f"(x), "=f"(y) : "l"(v));
}
__device__ __forceinline__ unsigned long long mul2(unsigned long long a, unsigned long long b) {
    unsigned long long d;
    asm("mul.rn.f32x2 %0, %1, %2;" : "=l"(d) : "l"(a), "l"(b));
    return d;
}
__device__ __forceinline__ void fma2(unsigned long long &d, unsigned long long a, unsigned long long b) {
    asm("fma.rn.f32x2 %0, %1, %2, %0;" : "+l"(d) : "l"(a), "l"(b));
}

// ---------------------------------------------------------------------------
// Kernel 1: per-row mean -> normalized triangular hat weights (exactly like ref)
// One block (256 threads) per row.
// ---------------------------------------------------------------------------
__global__ void kan_weights_kernel(const float* __restrict__ x) {
    const int row = blockIdx.x;
    const float4 v = reinterpret_cast<const float4*>(x + (size_t)row * IN_DIM)[threadIdx.x];
    float s = v.x + v.y + v.z + v.w;
    #pragma unroll
    for (int o = 16; o > 0; o >>= 1) s += __shfl_xor_sync(0xFFFFFFFFu, s, o);

    __shared__ float warp_sums[8];
    if ((threadIdx.x & 31) == 0) warp_sums[threadIdx.x >> 5] = s;
    __syncthreads();

    if (threadIdx.x == 0) {
        float tot = 0.0f;
        #pragma unroll
        for (int i = 0; i < 8; i++) tot += warp_sums[i];
        const float mean = tot * (1.0f / IN_DIM);

        float w[NGRID];
        float sum = 0.0f;
        #pragma unroll
        for (int g = 0; g < NGRID; g++) {
            const float gp = GRID_LO + HSTEP * (float)g;
            float t = 1.0f - fabsf(mean - gp) / HSTEP;
            t = t > 0.0f ? t : 0.0f;
            w[g] = t;
            sum += t;
        }
        const float inv = 1.0f / (sum + 1e-8f);
        #pragma unroll
        for (int g = 0; g < NGRID; g++) g_w[row * NGRID + g] = w[g] * inv;
    }
}

// ---------------------------------------------------------------------------
// Kernel 2: tiled active-segment GEMM.
//   out[m,n] = sum_{g active} w[m,g] * sum_k x[m,k] * coeff[g,n,k] + bias[n]
// Tile: BM=64 rows x BN=128 cols, BK=16. 256 threads, each computes 4x8 outputs.
// f32x2 packs over the K dimension (even/odd-k split accumulators).
// ---------------------------------------------------------------------------
#define BM 64
#define BN 128
#define BK 16
#define XS_PITCH 9     // float2 units per row (8 k-pairs + 1 pad)
#define CS_PITCH 129   // float2 units per k-pair row (128 n + 1 pad)

__global__ __launch_bounds__(256, 2)
void kan_gemm_kernel(const float* __restrict__ x,
                     const float* __restrict__ coeff,
                     const float* __restrict__ bias,
                     float* __restrict__ out) {
    const int tid = threadIdx.x;
    const int tc = tid & 15;   // column group: cols n0 + tc + 16*j, j=0..7
    const int tr = tid >> 4;   // row group:    rows m0 + tr*4 + r,  r=0..3
    const int m0 = blockIdx.y * BM;
    const int n0 = blockIdx.x * BN;

    __shared__ unsigned long long Xs[BM * XS_PITCH];   // {x[2k2], x[2k2+1]} at [m*9 + k2]
    __shared__ unsigned long long Cs[8 * CS_PITCH];    // {c[2k2], c[2k2+1]} at [k2*129 + n]
    __shared__ float wsm[BM * NGRID];
    __shared__ int act[NGRID];
    __shared__ int nact;

    // Load this tile's weights (contiguous) and build active-segment list.
    for (int i = tid; i < BM * NGRID; i += 256) wsm[i] = g_w[m0 * NGRID + i];
    if (tid == 0) nact = 0;
    __syncthreads();
    if (tid < NGRID) {
        bool any = false;
        for (int r = 0; r < BM; r++) any |= (wsm[r * NGRID + tid] != 0.0f);
        if (any) { int p = atomicAdd(&nact, 1); act[p] = tid; }
    }
    __syncthreads();
    const int NA = nact;

    unsigned long long acc[4][8];
    #pragma unroll
    for (int r = 0; r < 4; r++)
        #pragma unroll
        for (int j = 0; j < 8; j++) acc[r][j] = 0ull;

    const int xi = tid >> 2;        // 0..63
    const int xq = tid & 3;         // 0..3 -> k offset 4*xq

    for (int kb = 0; kb < IN_DIM; kb += BK) {
        __syncthreads();  // previous tile reads complete before overwrite

        // Load X tile (coalesced float4), store as k-pairs.
        {
            const float4 xv = *reinterpret_cast<const float4*>(
                x + (size_t)(m0 + xi) * IN_DIM + kb + 4 * xq);
            Xs[xi * XS_PITCH + 2 * xq]     = pack2(xv.x, xv.y);
            Xs[xi * XS_PITCH + 2 * xq + 1] = pack2(xv.z, xv.w);
        }

        for (int gi = 0; gi < NA; gi++) {
            const int g = act[gi];
            if (gi) __syncthreads();  // previous Cs reads complete

            // Load C_g tile (coalesced float4), store as k-pairs.
            #pragma unroll
            for (int p = 0; p < 2; p++) {
                const int idx = tid + p * 256;
                const int n = idx >> 2;
                const int q = idx & 3;
                const float4 cv = *reinterpret_cast<const float4*>(
                    coeff + (size_t)g * (OUT_DIM * IN_DIM)
                          + (size_t)(n0 + n) * IN_DIM + kb + 4 * q);
                Cs[(2 * q) * CS_PITCH + n]     = pack2(cv.x, cv.y);
                Cs[(2 * q + 1) * CS_PITCH + n] = pack2(cv.z, cv.w);
            }

            // Per-row weights for this segment, packed {w,w}.
            unsigned long long w2[4];
            #pragma unroll
            for (int r = 0; r < 4; r++) {
                const float w = wsm[(tr * 4 + r) * NGRID + g];
                w2[r] = pack2(w, w);
            }
            __syncthreads();

            // Inner product over 8 k-pairs.
            #pragma unroll
            for (int k2 = 0; k2 < 8; k2++) {
                unsigned long long a2[4];
                #pragma unroll
                for (int r = 0; r < 4; r++)
                    a2[r] = mul2(Xs[(tr * 4 + r) * XS_PITCH + k2], w2[r]);

                unsigned long long c2[8];
                #pragma unroll
                for (int j = 0; j < 8; j++)
                    c2[j] = Cs[k2 * CS_PITCH + 16 * j + tc];   // lanes tc consecutive: conflict-free

                #pragma unroll
                for (int r = 0; r < 4; r++)
                    #pragma unroll
                    for (int j = 0; j < 8; j++)
                        fma2(acc[r][j], a2[r], c2[j]);
            }
        }
    }

    // Epilogue: fold even/odd-k halves, add bias, store (coalesced across tc).
    #pragma unroll
    for (int r = 0; r < 4; r++) {
        const size_t m = (size_t)(m0 + tr * 4 + r);
        #pragma unroll
        for (int j = 0; j < 8; j++) {
            const int n = n0 + 16 * j + tc;
            float lo, hi;
            unpack2(acc[r][j], lo, hi);
            out[m * OUT_DIM + n] = lo + hi + bias[n];
        }
    }
}

// ---------------------------------------------------------------------------
// Launch
// ---------------------------------------------------------------------------
extern "C" void kernel_launch(void* const* d_in, const int* in_sizes, int n_in,
                              void* d_out, int out_size) {
    const float* x     = (const float*)d_in[0];   // (8,2048,1024) fp32
    const float* coeff = (const float*)d_in[1];   // (9,1024,1024) fp32
    const float* bias  = (const float*)d_in[2];   // (1024,)       fp32
    float* out = (float*)d_out;                   // (16384,1024)  fp32

    kan_weights_kernel<<<B_ROWS, 256>>>(x);

    dim3 grid(OUT_DIM / BN, B_ROWS / BM);  // (8, 256)
    kan_gemm_kernel<<<grid, 256>>>(x, coeff, bias, out);
}

// round 5
// speedup vs baseline: 6.6911x; 6.6911x over previous
#include <cuda_runtime.h>
#include <cuda_fp16.h>
#include <cstdint>

#define B_ROWS   16384
#define IN_DIM   1024
#define OUT_DIM  1024
#define NGRID    9
#define GRID_LO  (-1.0f)
#define HSTEP    0.25f

#define MTILE 128
#define NTILE 128
#define BK    32
#define NUM_MT (B_ROWS / MTILE)        // 128
#define STAGES 3
#define A_BYTES 8192                   // 128 rows x 64B
#define STAGE_BYTES 16384              // A + B
#define DSMEM_BYTES (STAGES * STAGE_BYTES)   // 49152

// ---------------- device scratch ----------------
__device__ float   g_w[B_ROWS * NGRID];
__device__ __half  g_ax[(size_t)NGRID * B_ROWS * IN_DIM];    // w-scaled X, fp16
__device__ __half  g_cf[(size_t)NGRID * OUT_DIM * IN_DIM];   // coeff, fp16
__device__ int     g_tcnt[NUM_MT];
__device__ int     g_tlist[NUM_MT * NGRID];
__device__ int     g_gmask;

// ---------------- helpers ----------------
__device__ __forceinline__ uint32_t smem_u32(const void* p) {
    uint32_t a;
    asm("{ .reg .u64 t; cvta.to.shared.u64 t, %1; cvt.u32.u64 %0, t; }" : "=r"(a) : "l"(p));
    return a;
}
__device__ __forceinline__ void cp16(uint32_t dst, const void* src) {
    asm volatile("cp.async.cg.shared.global [%0], [%1], 16;" :: "r"(dst), "l"(src) : "memory");
}
// swizzled byte offset inside a [rows][32 halfs] tile (64B pitch)
__device__ __forceinline__ uint32_t swz(int r, int c) {
    return (uint32_t)(r * 64 + ((c ^ ((r >> 1) & 3)) << 4));
}
#define LDSM_X4(r0, r1, r2, r3, addr) \
    asm volatile("ldmatrix.sync.aligned.m8n8.x4.shared.b16 {%0,%1,%2,%3}, [%4];" \
        : "=r"(r0), "=r"(r1), "=r"(r2), "=r"(r3) : "r"(addr))
#define MMA16816(d, a, b) \
    asm volatile("mma.sync.aligned.m16n8k16.row.col.f32.f16.f16.f32 " \
        "{%0,%1,%2,%3}, {%4,%5,%6,%7}, {%8,%9}, {%0,%1,%2,%3};" \
        : "+f"((d)[0]), "+f"((d)[1]), "+f"((d)[2]), "+f"((d)[3]) \
        : "r"((a)[0]), "r"((a)[1]), "r"((a)[2]), "r"((a)[3]), "r"((b)[0]), "r"((b)[1]))

// ---------------------------------------------------------------------------
// Kernel 1: per-row mean -> normalized hat weights (exact, like reference)
// ---------------------------------------------------------------------------
__global__ void kan_weights_kernel(const float* __restrict__ x) {
    if (blockIdx.x == 0 && threadIdx.x == 0) g_gmask = 0;  // reset for tilelist pass
    const int row = blockIdx.x;
    const float4 v = reinterpret_cast<const float4*>(x + (size_t)row * IN_DIM)[threadIdx.x];
    float s = v.x + v.y + v.z + v.w;
    #pragma unroll
    for (int o = 16; o > 0; o >>= 1) s += __shfl_xor_sync(0xFFFFFFFFu, s, o);

    __shared__ float warp_sums[8];
    if ((threadIdx.x & 31) == 0) warp_sums[threadIdx.x >> 5] = s;
    __syncthreads();

    if (threadIdx.x == 0) {
        float tot = 0.0f;
        #pragma unroll
        for (int i = 0; i < 8; i++) tot += warp_sums[i];
        const float mean = tot * (1.0f / IN_DIM);
        float w[NGRID]; float sum = 0.0f;
        #pragma unroll
        for (int g = 0; g < NGRID; g++) {
            const float gp = GRID_LO + HSTEP * (float)g;
            float t = 1.0f - fabsf(mean - gp) / HSTEP;
            t = t > 0.0f ? t : 0.0f;
            w[g] = t; sum += t;
        }
        const float inv = 1.0f / (sum + 1e-8f);
        #pragma unroll
        for (int g = 0; g < NGRID; g++) g_w[row * NGRID + g] = w[g] * inv;
    }
}

// ---------------------------------------------------------------------------
// Kernel 2: per-M-tile (128 rows) active segment list + global segment mask
// ---------------------------------------------------------------------------
__global__ void kan_tilelist_kernel() {
    __shared__ int mask;
    if (threadIdx.x == 0) mask = 0;
    __syncthreads();
    const int row = blockIdx.x * MTILE + threadIdx.x;
    int m = 0;
    #pragma unroll
    for (int g = 0; g < NGRID; g++)
        if (g_w[row * NGRID + g] != 0.0f) m |= (1 << g);
    atomicOr(&mask, m);
    __syncthreads();
    if (threadIdx.x == 0) {
        int c = 0;
        #pragma unroll
        for (int g = 0; g < NGRID; g++)
            if ((mask >> g) & 1) g_tlist[blockIdx.x * NGRID + c++] = g;
        g_tcnt[blockIdx.x] = c;
        atomicOr(&g_gmask, mask);
    }
}

// ---------------------------------------------------------------------------
// Kernel 3: w-scaled X -> fp16 for every segment in the row's tile list
// ---------------------------------------------------------------------------
__global__ void kan_scale_kernel(const float* __restrict__ x) {
    const int row = blockIdx.x;
    const int tile = row >> 7;
    const int cnt = g_tcnt[tile];
    const float4 v = reinterpret_cast<const float4*>(x + (size_t)row * IN_DIM)[threadIdx.x];
    for (int gi = 0; gi < cnt; gi++) {
        const int g = g_tlist[tile * NGRID + gi];
        const float w = g_w[row * NGRID + g];
        __half2 h0 = __floats2half2_rn(w * v.x, w * v.y);
        __half2 h1 = __floats2half2_rn(w * v.z, w * v.w);
        uint2 u;
        u.x = *reinterpret_cast<uint32_t*>(&h0);
        u.y = *reinterpret_cast<uint32_t*>(&h1);
        *reinterpret_cast<uint2*>(&g_ax[((size_t)g << 24) + ((size_t)row << 10) + threadIdx.x * 4]) = u;
    }
}

// ---------------------------------------------------------------------------
// Kernel 4: coeff fp32 -> fp16, only for segments used by some tile
// ---------------------------------------------------------------------------
__global__ void kan_cvt_coeff_kernel(const float* __restrict__ coeff) {
    const int g = blockIdx.x >> 9;            // 512 blocks per segment
    if (!((g_gmask >> g) & 1)) return;
    const size_t base = ((size_t)blockIdx.x * 256 + threadIdx.x) * 8;
    const float4 a = *reinterpret_cast<const float4*>(coeff + base);
    const float4 b = *reinterpret_cast<const float4*>(coeff + base + 4);
    __half2 h0 = __floats2half2_rn(a.x, a.y);
    __half2 h1 = __floats2half2_rn(a.z, a.w);
    __half2 h2 = __floats2half2_rn(b.x, b.y);
    __half2 h3 = __floats2half2_rn(b.z, b.w);
    uint4 u;
    u.x = *reinterpret_cast<uint32_t*>(&h0);
    u.y = *reinterpret_cast<uint32_t*>(&h1);
    u.z = *reinterpret_cast<uint32_t*>(&h2);
    u.w = *reinterpret_cast<uint32_t*>(&h3);
    *reinterpret_cast<uint4*>(&g_cf[base]) = u;
}

// ---------------------------------------------------------------------------
// Kernel 5: HMMA GEMM, concat-K over active segments.
// CTA 128x128, BK=32, 3-stage cp.async pipeline, 8 warps (2M x 4N), warp 64x32.
// ---------------------------------------------------------------------------
__global__ void __launch_bounds__(256, 2)
kan_hmma_kernel(const float* __restrict__ bias, float* __restrict__ out) {
    extern __shared__ unsigned char dyn_smem[];
    __shared__ int s_na, s_list[NGRID];

    const int tid  = threadIdx.x;
    const int wid  = tid >> 5;
    const int lane = tid & 31;
    const int wm = wid >> 2;          // 0..1 -> M offset wm*64
    const int wn = wid & 3;           // 0..3 -> N offset wn*32
    const int m0 = blockIdx.y * MTILE;
    const int n0 = blockIdx.x * NTILE;
    const uint32_t dynb = smem_u32(dyn_smem);

    if (tid == 0) s_na = g_tcnt[blockIdx.y];
    if (tid < NGRID) s_list[tid] = g_tlist[blockIdx.y * NGRID + tid];
    __syncthreads();
    const int NA = s_na;
    const int total = NA * (IN_DIM / BK);   // NA * 32

    float acc[4][4][4];
    #pragma unroll
    for (int mi = 0; mi < 4; mi++)
        #pragma unroll
        for (int ni = 0; ni < 4; ni++)
            #pragma unroll
            for (int e = 0; e < 4; e++) acc[mi][ni][e] = 0.0f;

    // Per-thread load coordinates: 2 consecutive 16B chunks of A and of B.
    const int ch = tid * 2;
    const int lr = ch >> 2;           // row 0..127
    const int lc = ch & 3;            // chunk 0 or 2

    // ---- prologue ----
    #pragma unroll
    for (int s = 0; s < STAGES - 1; s++) {
        if (s < total) {
            const int g  = s_list[s >> 5];
            const int kb = (s & 31) * BK;
            const uint32_t sa = dynb + s * STAGE_BYTES;
            const __half* ap = g_ax + ((size_t)g << 24) + ((size_t)(m0 + lr) << 10) + kb + lc * 8;
            const __half* bp = g_cf + ((size_t)g << 20) + ((size_t)(n0 + lr) << 10) + kb + lc * 8;
            cp16(sa + swz(lr, lc),               ap);
            cp16(sa + swz(lr, lc + 1),           ap + 8);
            cp16(sa + A_BYTES + swz(lr, lc),     bp);
            cp16(sa + A_BYTES + swz(lr, lc + 1), bp + 8);
        }
        asm volatile("cp.async.commit_group;" ::: "memory");
    }

    // ---- main loop ----
    for (int it = 0; it < total; it++) {
        asm volatile("cp.async.wait_group %0;" :: "n"(STAGES - 2));
        __syncthreads();

        const int nxt = it + STAGES - 1;
        if (nxt < total) {
            const int g  = s_list[nxt >> 5];
            const int kb = (nxt & 31) * BK;
            const uint32_t sa = dynb + (nxt % STAGES) * STAGE_BYTES;
            const __half* ap = g_ax + ((size_t)g << 24) + ((size_t)(m0 + lr) << 10) + kb + lc * 8;
            const __half* bp = g_cf + ((size_t)g << 20) + ((size_t)(n0 + lr) << 10) + kb + lc * 8;
            cp16(sa + swz(lr, lc),               ap);
            cp16(sa + swz(lr, lc + 1),           ap + 8);
            cp16(sa + A_BYTES + swz(lr, lc),     bp);
            cp16(sa + A_BYTES + swz(lr, lc + 1), bp + 8);
        }
        asm volatile("cp.async.commit_group;" ::: "memory");

        const uint32_t aBase = dynb + (it % STAGES) * STAGE_BYTES;
        const uint32_t bBase = aBase + A_BYTES;

        #pragma unroll
        for (int h = 0; h < 2; h++) {
            uint32_t a[4][4], b[4][2];
            #pragma unroll
            for (int mi = 0; mi < 4; mi++) {
                const int r = wm * 64 + mi * 16 + (lane & 15);
                const int c = 2 * h + (lane >> 4);
                LDSM_X4(a[mi][0], a[mi][1], a[mi][2], a[mi][3], aBase + swz(r, c));
            }
            #pragma unroll
            for (int nj = 0; nj < 2; nj++) {
                const int r = wn * 32 + nj * 16 + ((lane & 16) >> 1) + (lane & 7);
                const int c = 2 * h + ((lane >> 3) & 1);
                LDSM_X4(b[2 * nj][0], b[2 * nj][1], b[2 * nj + 1][0], b[2 * nj + 1][1],
                        bBase + swz(r, c));
            }
            #pragma unroll
            for (int mi = 0; mi < 4; mi++)
                #pragma unroll
                for (int ni = 0; ni < 4; ni++)
                    MMA16816(acc[mi][ni], a[mi], b[ni]);
        }
    }

    // ---- epilogue: add bias, store float2 per fragment half ----
    #pragma unroll
    for (int ni = 0; ni < 4; ni++) {
        const int col = n0 + wn * 32 + ni * 8 + 2 * (lane & 3);
        const float2 bb = *reinterpret_cast<const float2*>(bias + col);
        #pragma unroll
        for (int mi = 0; mi < 4; mi++) {
            const int row = m0 + wm * 64 + mi * 16 + (lane >> 2);
            float2 o0, o1;
            o0.x = acc[mi][ni][0] + bb.x;
            o0.y = acc[mi][ni][1] + bb.y;
            o1.x = acc[mi][ni][2] + bb.x;
            o1.y = acc[mi][ni][3] + bb.y;
            *reinterpret_cast<float2*>(&out[(size_t)row * OUT_DIM + col]) = o0;
            *reinterpret_cast<float2*>(&out[(size_t)(row + 8) * OUT_DIM + col]) = o1;
        }
    }
}

// ---------------------------------------------------------------------------
// Launch
// ---------------------------------------------------------------------------
extern "C" void kernel_launch(void* const* d_in, const int* in_sizes, int n_in,
                              void* d_out, int out_size) {
    const float* x     = (const float*)d_in[0];   // (8,2048,1024) fp32
    const float* coeff = (const float*)d_in[1];   // (9,1024,1024) fp32
    const float* bias  = (const float*)d_in[2];   // (1024,)       fp32
    float* out = (float*)d_out;                   // (16384,1024)  fp32

    cudaFuncSetAttribute(kan_hmma_kernel,
                         cudaFuncAttributeMaxDynamicSharedMemorySize, DSMEM_BYTES);

    kan_weights_kernel<<<B_ROWS, 256>>>(x);
    kan_tilelist_kernel<<<NUM_MT, MTILE>>>();
    kan_scale_kernel<<<B_ROWS, 256>>>(x);
    kan_cvt_coeff_kernel<<<NGRID * 512, 256>>>(coeff);

    dim3 grid(OUT_DIM / NTILE, NUM_MT);   // (8, 128)
    kan_hmma_kernel<<<grid, 256, DSMEM_BYTES>>>(bias, out);
}